// round 5
// baseline (speedup 1.0000x reference)
#include <cuda_runtime.h>

#define B 16
#define G 5000
#define K 256
#define HID 64
#define STEPS 10
#define NB 148            // grid = #SMs, 1 CTA/SM -> all resident, barriers safe
#define NG1 34            // genes/block in P1 (148*34 = 5032 >= 5000)
#define NG3 38            // genes/block in P3 (132*38 = 5016 >= 5000)
#define AS_ROW 260
#define SM_FLOATS 34824   // union smem (P2 view is the max)

// Scratch (zero-init at load; all cross-replay state idempotent/monotone)
__device__ unsigned g_tmodU[B * K];          // atomicMax(float-as-uint), idempotent
__device__ __align__(16) float g_Z[B][K];
__device__ float g_coff[B];
__device__ unsigned long long g_c1, g_c2;    // monotone barrier counters

#define FMAXUPD(ACC, T, MV)                         \
    ACC.x = fmaxf(ACC.x, (T) * MV.x);               \
    ACC.y = fmaxf(ACC.y, (T) * MV.y);               \
    ACC.z = fmaxf(ACC.z, (T) * MV.z);               \
    ACC.w = fmaxf(ACC.w, (T) * MV.w);

__global__ __launch_bounds__(1024, 1) void fused_all(
    const float* __restrict__ ctl,
    const float* __restrict__ tgt,
    const int*   __restrict__ cell_idx,
    const float* __restrict__ M,
    const float* __restrict__ A,
    const float* __restrict__ W1,
    const float* __restrict__ b1,
    const float* __restrict__ cell_emb,
    const float* __restrict__ W2,
    const float* __restrict__ b2,
    float* __restrict__ out)
{
    extern __shared__ float sm[];
    const int tid = threadIdx.x;
    const int bid = blockIdx.x;

    // ======================= P1: max-pool (all blocks) ====================
    {
        float*  ts   = sm;                    // [B][NG1] = 544 floats
        float4* red4 = (float4*)(sm + 1024);  // [(ge,h,ii)][q4] = 4096 float4

        const int g0 = bid * NG1;
        for (int i = tid; i < B * NG1; i += 1024) {
            int g = g0 + (i % NG1);
            ts[i] = (g < G) ? tgt[(i / NG1) * G + g] : 0.0f;
        }
        __syncthreads();

        const int q4 = tid & 63;          // k-quad
        const int h  = (tid >> 6) & 3;    // b-quad
        const int ge = tid >> 8;          // gene subset (gl = ge, ge+4, ...)

        float4 acc0 = make_float4(0.f, 0.f, 0.f, 0.f);
        float4 acc1 = acc0, acc2 = acc0, acc3 = acc0;

#pragma unroll
        for (int i0 = 0; i0 < 9; i0 += 3) {
            float4 mv[3];
#pragma unroll
            for (int u = 0; u < 3; u++) {
                int gl = ge + 4 * (i0 + u);
                int g  = g0 + gl;
                mv[u] = (gl < NG1 && g < G)
                      ? *(const float4*)(M + (size_t)g * K + 4 * q4)
                      : make_float4(0.f, 0.f, 0.f, 0.f);
            }
#pragma unroll
            for (int u = 0; u < 3; u++) {
                int gl = min(ge + 4 * (i0 + u), NG1 - 1); // mv==0 if invalid
                float4 m = mv[u];
                float t0 = ts[(4 * h + 0) * NG1 + gl];
                float t1 = ts[(4 * h + 1) * NG1 + gl];
                float t2 = ts[(4 * h + 2) * NG1 + gl];
                float t3 = ts[(4 * h + 3) * NG1 + gl];
                FMAXUPD(acc0, t0, m)
                FMAXUPD(acc1, t1, m)
                FMAXUPD(acc2, t2, m)
                FMAXUPD(acc3, t3, m)
            }
        }

        const int base = ((ge * 4 + h) * 4) * 64 + q4;
        red4[base]       = acc0;
        red4[base + 64]  = acc1;
        red4[base + 128] = acc2;
        red4[base + 192] = acc3;
        __syncthreads();

        if (tid < 256) {
            int q4r = tid & 63, hr = tid >> 6;
#pragma unroll
            for (int ii = 0; ii < 4; ii++) {
                float4 a = red4[((0 * 4 + hr) * 4 + ii) * 64 + q4r];
                float4 c = red4[((1 * 4 + hr) * 4 + ii) * 64 + q4r];
                float4 d = red4[((2 * 4 + hr) * 4 + ii) * 64 + q4r];
                float4 e = red4[((3 * 4 + hr) * 4 + ii) * 64 + q4r];
                float4 r;
                r.x = fmaxf(fmaxf(a.x, c.x), fmaxf(d.x, e.x));
                r.y = fmaxf(fmaxf(a.y, c.y), fmaxf(d.y, e.y));
                r.z = fmaxf(fmaxf(a.z, c.z), fmaxf(d.z, e.z));
                r.w = fmaxf(fmaxf(a.w, c.w), fmaxf(d.w, e.w));
                int bb = 4 * hr + ii;
                unsigned* dst = &g_tmodU[bb * K + 4 * q4r];
                atomicMax(dst + 0, __float_as_uint(r.x));
                atomicMax(dst + 1, __float_as_uint(r.y));
                atomicMax(dst + 2, __float_as_uint(r.z));
                atomicMax(dst + 3, __float_as_uint(r.w));
            }
        }
        __threadfence();
        __syncthreads();
    }

    // Barrier-1 arrival (all blocks). Epoch from own position: replay-safe.
    unsigned long long Lnum = 0;
    if (tid == 0) {
        unsigned long long pos = atomicAdd(&g_c1, 1ULL);
        Lnum = pos / NB;
    }

    if (bid < B) {
        // ==================== P2: APPNP (blocks 0..15) ====================
        if (tid == 0) {
            unsigned long long t1 = (Lnum + 1) * (unsigned long long)NB;
            while (*(volatile unsigned long long*)&g_c1 < t1) __nanosleep(64);
            __threadfence();
        }
        __syncthreads();

        float* As   = sm;                     // 128 x 260
        float* Zs   = sm + 128 * AS_ROW;      // 256
        float* Ss   = Zs + 256;               // 256
        float* pred = Ss + 256;               // 1024
        const int b = bid;
        const int q = tid >> 8;
        const int k = tid & 255;

        if (q == 0) {
            float v = __uint_as_float(g_tmodU[b * K + k]);
            Ss[k] = v;
            Zs[k] = v;
        }
        if (tid >= 992) {                     // cell offset
            int lane = tid - 992;
            int ci = cell_idx[b];
            float v = cell_emb[ci * HID + lane] * W2[lane]
                    + cell_emb[ci * HID + 32 + lane] * W2[32 + lane];
#pragma unroll
            for (int o = 16; o > 0; o >>= 1)
                v += __shfl_down_sync(0xffffffffu, v, o);
            if (lane == 0) g_coff[b] = v + b2[0];
        }

        // register half of A: rows [64q+32, 64q+64), staged via slab 0
        float regA[32];
#pragma unroll 1
        for (int c0 = 0; c0 < 4; c0++) {
            __syncthreads();
            for (int idx = tid; idx < 32 * 64; idx += 1024) {
                int r = idx >> 6, cq = idx & 63;
                *(float4*)(As + r * AS_ROW + 4 * cq) =
                    *(const float4*)(A + (64 * c0 + 32 + r) * K + 4 * cq);
            }
            __syncthreads();
            if (q == c0) {
#pragma unroll
                for (int r = 0; r < 32; r++)
                    regA[r] = As[r * AS_ROW + k];
            }
        }
        __syncthreads();

        // smem half: rows with (j&63)<32 at slab l = (j>>6)*32 + (j&31)
        for (int idx = tid; idx < 128 * 64; idx += 1024) {
            int l = idx >> 6, cq = idx & 63;
            int j = ((l >> 5) << 6) + (l & 31);
            *(float4*)(As + l * AS_ROW + 4 * cq) =
                *(const float4*)(A + j * K + 4 * cq);
        }
        __syncthreads();

        const float* AsQ = As + (q * 32) * AS_ROW + k;
        const float* Zq  = Zs + 64 * q;
#pragma unroll 1
        for (int s = 0; s < STEPS; s++) {
            float a0 = 0.f, a1 = 0.f;
#pragma unroll
            for (int i4 = 0; i4 < 8; i4++) {
                float4 z = *(const float4*)(Zq + i4 * 4);
                a0 = fmaf(AsQ[(i4 * 4 + 0) * AS_ROW], z.x, a0);
                a1 = fmaf(AsQ[(i4 * 4 + 1) * AS_ROW], z.y, a1);
                a0 = fmaf(AsQ[(i4 * 4 + 2) * AS_ROW], z.z, a0);
                a1 = fmaf(AsQ[(i4 * 4 + 3) * AS_ROW], z.w, a1);
            }
#pragma unroll
            for (int i4 = 0; i4 < 8; i4++) {
                float4 z = *(const float4*)(Zq + 32 + i4 * 4);
                a0 = fmaf(regA[i4 * 4 + 0], z.x, a0);
                a1 = fmaf(regA[i4 * 4 + 1], z.y, a1);
                a0 = fmaf(regA[i4 * 4 + 2], z.z, a0);
                a1 = fmaf(regA[i4 * 4 + 3], z.w, a1);
            }
            pred[tid] = a0 + a1;
            __syncthreads();
            if (q == 0) {
                float v = pred[k] + pred[256 + k] + pred[512 + k] + pred[768 + k];
                Zs[k] = 0.9f * v + 0.1f * Ss[k];
            }
            __syncthreads();
        }
        if (q == 0) g_Z[b][k] = Zs[k];

        __threadfence();
        __syncthreads();
        if (tid == 0) atomicAdd(&g_c2, 1ULL);
        return;
    }

    // =============== P3: z_gene + MLP + out (blocks 16..147) ==============
    {
        float*  Ms    = sm;                         // 38*257 = 9766
        float2* Zp    = (float2*)(sm + 9768);       // [K][8] = 2048 float2
        float2* zpart = (float2*)(sm + 13864);      // [3][304]
        float*  ctls  = sm + 15688;                 // [B][NG3] = 608
        float*  tts   = ctls + 608;
        float*  W1s   = tts + 608;                  // 192
        float*  b1s   = W1s + 192;
        float*  W2s   = b1s + 64;
        float*  coffs = W2s + 64;                   // 16

        const int p3 = bid - B;
        const int g0 = p3 * NG3;

        // Pre-stage everything that doesn't depend on Z (overlaps P2)
        for (int i = tid; i < NG3 * 64; i += 1024) {
            int gl = i >> 6, jq = i & 63;
            int g = g0 + gl;
            float4 v = (g < G) ? *(const float4*)(M + (size_t)g * K + 4 * jq)
                               : make_float4(0.f, 0.f, 0.f, 0.f);
            float* d = Ms + gl * 257 + 4 * jq;
            d[0] = v.x; d[1] = v.y; d[2] = v.z; d[3] = v.w;
        }
        for (int i = tid; i < B * NG3; i += 1024) {
            int b = i / NG3, gl = i % NG3;
            int g = g0 + gl;
            ctls[i] = (g < G) ? ctl[b * G + g] : 0.0f;
            tts[i]  = (g < G) ? tgt[b * G + g] : 0.0f;
        }
        if (tid < 3 * HID) W1s[tid] = W1[tid];
        if (tid < HID) { b1s[tid] = b1[tid]; W2s[tid] = W2[tid]; }

        // Wait for all 16 P2 blocks
        if (tid == 0) {
            unsigned long long t2 = (Lnum + 1) * (unsigned long long)B;
            while (*(volatile unsigned long long*)&g_c2 < t2) __nanosleep(64);
            __threadfence();
        }
        __syncthreads();

        for (int i = tid; i < K * 8; i += 1024) {
            int j = i >> 3, p = i & 7;
            Zp[i] = make_float2(g_Z[p][j], g_Z[p + 8][j]);
        }
        if (tid < B) coffs[tid] = g_coff[tid];
        __syncthreads();

        // z-dot partials: 912 workers = (jh in 0..2) x (p in 0..7) x (gl in 0..37)
        if (tid < 912) {
            int jh = tid / 304, r = tid % 304;
            int p = r & 7, gl = r >> 3;
            int j0 = (jh == 0) ? 0 : (jh == 1) ? 86 : 172;
            int j1 = (jh == 0) ? 86 : (jh == 1) ? 172 : 256;
            float z0 = 0.f, z1 = 0.f;
            const float*  Mrow = Ms + gl * 257;
            const float2* Zw   = Zp + p;
            for (int j = j0; j < j1; j++) {
                float  m  = Mrow[j];
                float2 zz = Zw[j * 8];
                z0 = fmaf(zz.x, m, z0);
                z1 = fmaf(zz.y, m, z1);
            }
            zpart[jh * 304 + r] = make_float2(z0, z1);
        }
        __syncthreads();

        if (tid < 304) {
            int p = tid & 7, gl = tid >> 3;
            int g = g0 + gl;
            if (g < G) {
                float2 pa = zpart[tid], pb = zpart[304 + tid], pc = zpart[608 + tid];
                float z0 = pa.x + pb.x + pc.x;
                float z1 = pa.y + pb.y + pc.y;
                float c0 = ctls[p * NG3 + gl], c1v = ctls[(p + 8) * NG3 + gl];
                float t0 = tts[p * NG3 + gl],  t1v = tts[(p + 8) * NG3 + gl];
                float y0 = coffs[p], y1 = coffs[p + 8];
#pragma unroll 8
                for (int j = 0; j < HID; j++) {
                    float w1c = W1s[j], w1t = W1s[HID + j], w1z = W1s[2 * HID + j];
                    float bbv = b1s[j], w2 = W2s[j];
                    float v0 = fmaf(c0, w1c, fmaf(t0, w1t, fmaf(z0, w1z, bbv)));
                    float v1 = fmaf(c1v, w1c, fmaf(t1v, w1t, fmaf(z1, w1z, bbv)));
                    y0 = fmaf(fmaxf(v0, 0.f), w2, y0);
                    y1 = fmaf(fmaxf(v1, 0.f), w2, y1);
                }
                out[p * G + g]       = y0;
                out[(p + 8) * G + g] = y1;
            }
        }
    }
}

// ---------------------------------------------------------------------------
// metadata order: ctl, drug_targets, cell_idx, drug_fp, M, A, W1, b1,
//                 cell_emb, W2, b2   -> output [B, G] float32
// ---------------------------------------------------------------------------
extern "C" void kernel_launch(void* const* d_in, const int* in_sizes, int n_in,
                              void* d_out, int out_size)
{
    const float* ctl      = (const float*)d_in[0];
    const float* tgt      = (const float*)d_in[1];
    const int*   cell_idx = (const int*)  d_in[2];
    // d_in[3] = drug_fp (unused by the model)
    const float* M        = (const float*)d_in[4];
    const float* A        = (const float*)d_in[5];
    const float* W1       = (const float*)d_in[6];
    const float* b1       = (const float*)d_in[7];
    const float* cell_emb = (const float*)d_in[8];
    const float* W2       = (const float*)d_in[9];
    const float* b2       = (const float*)d_in[10];
    float* out = (float*)d_out;

    const int smem = SM_FLOATS * (int)sizeof(float);
    cudaFuncSetAttribute(fused_all,
                         cudaFuncAttributeMaxDynamicSharedMemorySize, smem);

    fused_all<<<NB, 1024, smem>>>(ctl, tgt, cell_idx, M, A, W1, b1,
                                  cell_emb, W2, b2, out);
}

// round 6
// speedup vs baseline: 1.1024x; 1.1024x over previous
#include <cuda_runtime.h>

#define B 16
#define G 5000
#define K 256
#define HID 64
#define STEPS 10
#define NCHUNK 160
#define NG1 32            // genes/block in K1 (160*32 = 5120 >= 5000)
#define GT 32             // genes/block in K3 (157 blocks)
#define AS_ROW 260

// Scratch (no allocations allowed)
__device__ __align__(16) float g_partial[NCHUNK][B][K];  // 2.6 MB
__device__ __align__(16) float g_Z[B][K];
__device__ float g_coff[B];

#define FMAXUPD(ACC, T, MV)                         \
    ACC.x = fmaxf(ACC.x, (T) * MV.x);               \
    ACC.y = fmaxf(ACC.y, (T) * MV.y);               \
    ACC.z = fmaxf(ACC.z, (T) * MV.z);               \
    ACC.w = fmaxf(ACC.w, (T) * MV.w);

// ---------------------------------------------------------------------------
// K1: max-pool. 160 blocks x 1024 threads (32 warps/SM).
// Thread (q4 = tid&63, h = (tid>>6)&3, ge = tid>>8): b-quad h, k-quad q4,
// genes ge, ge+4, ... (8 of 32). Two 4-deep load groups (MLP=4/thread,
// 32 warps/SM -> plenty in flight). Products >= 0 so init 0 is exact.
// ---------------------------------------------------------------------------
__global__ __launch_bounds__(1024) void k1_maxpool(
    const float* __restrict__ t, const float* __restrict__ M)
{
    extern __shared__ float s1[];
    float*  ts   = s1;                    // [B][NG1] = 512
    float4* red4 = (float4*)(s1 + 512);   // [64][64] float4 = 64 KB

    const int tid = threadIdx.x;
    const int g0  = blockIdx.x * NG1;

    for (int i = tid; i < B * NG1; i += 1024) {
        int g = g0 + (i & 31);
        ts[i] = (g < G) ? t[(i >> 5) * G + g] : 0.0f;
    }
    __syncthreads();

    const int q4 = tid & 63;
    const int h  = (tid >> 6) & 3;
    const int ge = tid >> 8;

    float4 acc[4];
#pragma unroll
    for (int ii = 0; ii < 4; ii++) acc[ii] = make_float4(0.f, 0.f, 0.f, 0.f);

#pragma unroll
    for (int i0 = 0; i0 < 8; i0 += 4) {
        float4 mv[4];
#pragma unroll
        for (int u = 0; u < 4; u++) {
            int gl = ge + 4 * (i0 + u);
            int g  = g0 + gl;
            mv[u] = (g < G) ? *(const float4*)(M + (size_t)g * K + 4 * q4)
                            : make_float4(0.f, 0.f, 0.f, 0.f);
        }
#pragma unroll
        for (int u = 0; u < 4; u++) {
            int gl = ge + 4 * (i0 + u);
            float4 m = mv[u];
#pragma unroll
            for (int ii = 0; ii < 4; ii++) {
                float tv = ts[(4 * h + ii) * NG1 + gl];
                FMAXUPD(acc[ii], tv, m)
            }
        }
    }

#pragma unroll
    for (int ii = 0; ii < 4; ii++)
        red4[(((ge * 4 + h) * 4 + ii) << 6) + q4] = acc[ii];
    __syncthreads();

    if (tid < 256) {
        int q4r = tid & 63, hr = tid >> 6;
#pragma unroll
        for (int ii = 0; ii < 4; ii++) {
            float4 a = red4[(((0 * 4 + hr) * 4 + ii) << 6) + q4r];
            float4 c = red4[(((1 * 4 + hr) * 4 + ii) << 6) + q4r];
            float4 d = red4[(((2 * 4 + hr) * 4 + ii) << 6) + q4r];
            float4 e = red4[(((3 * 4 + hr) * 4 + ii) << 6) + q4r];
            float4 r;
            r.x = fmaxf(fmaxf(a.x, c.x), fmaxf(d.x, e.x));
            r.y = fmaxf(fmaxf(a.y, c.y), fmaxf(d.y, e.y));
            r.z = fmaxf(fmaxf(a.z, c.z), fmaxf(d.z, e.z));
            r.w = fmaxf(fmaxf(a.w, c.w), fmaxf(d.w, e.w));
            *(float4*)(&g_partial[blockIdx.x][4 * hr + ii][4 * q4r]) = r;
        }
    }
}
#define K1_SMEM ((512 + 64 * 64 * 4) * (int)sizeof(float))

// ---------------------------------------------------------------------------
// K2: reduce partials -> t_mod, 10-step APPNP. 16 blocks x 1024 threads.
// Thread (q = tid>>8, k = tid&255) owns j in [64q, 64q+64): rows
// [64q+32,64q+64) in registers (loaded DIRECTLY from global, MLP=32),
// rows [64q,64q+32) in smem (conflict-free row-major, consecutive-k lanes).
// ---------------------------------------------------------------------------
#define K2_SMEM_FLOATS (128 * AS_ROW + 256 + 256 + 1024)

__global__ __launch_bounds__(1024, 1) void k2_appnp(
    const float* __restrict__ A,
    const int*   __restrict__ cell_idx,
    const float* __restrict__ cell_emb,
    const float* __restrict__ W2,
    const float* __restrict__ b2)
{
    extern __shared__ float sm[];
    float* As   = sm;                     // 128 x 260
    float* Zs   = sm + 128 * AS_ROW;
    float* Ss   = Zs + 256;
    float* pred = Ss + 256;

    const int tid = threadIdx.x;
    const int b   = blockIdx.x;
    const int q   = tid >> 8;
    const int k   = tid & 255;

    // regA: direct coalesced global loads, 32-deep MLP
    float regA[32];
#pragma unroll
    for (int r = 0; r < 32; r++)
        regA[r] = A[(64 * q + 32 + r) * K + k];

    // smem half: rows with (j&63)<32 at slab l = (j>>6)*32 + (j&31)
    for (int idx = tid; idx < 128 * 64; idx += 1024) {
        int l = idx >> 6, cq = idx & 63;
        int j = ((l >> 5) << 6) + (l & 31);
        *(float4*)(As + l * AS_ROW + 4 * cq) =
            *(const float4*)(A + j * K + 4 * cq);
    }

    // t_mod reduction: 160 chunks, 40 per q-group
    {
        float m = 0.0f;
        const float* gp = &g_partial[q * 40][b][k];
#pragma unroll 8
        for (int c = 0; c < 40; c++)
            m = fmaxf(m, gp[c * (B * K)]);
        pred[tid] = m;
    }

    // cell offset: top warp
    if (tid >= 992) {
        int lane = tid - 992;
        int ci = cell_idx[b];
        float v = cell_emb[ci * HID + lane] * W2[lane]
                + cell_emb[ci * HID + 32 + lane] * W2[32 + lane];
#pragma unroll
        for (int o = 16; o > 0; o >>= 1)
            v += __shfl_down_sync(0xffffffffu, v, o);
        if (lane == 0) g_coff[b] = v + b2[0];
    }
    __syncthreads();

    if (q == 0) {
        float v = fmaxf(fmaxf(pred[k], pred[256 + k]),
                        fmaxf(pred[512 + k], pred[768 + k]));
        Ss[k] = v;
        Zs[k] = v;
    }
    __syncthreads();

    const float* AsQ = As + (q * 32) * AS_ROW + k;
    const float* Zq  = Zs + 64 * q;
#pragma unroll 1
    for (int s = 0; s < STEPS; s++) {
        float a0 = 0.f, a1 = 0.f;
#pragma unroll
        for (int i4 = 0; i4 < 8; i4++) {
            float4 z = *(const float4*)(Zq + i4 * 4);
            a0 = fmaf(AsQ[(i4 * 4 + 0) * AS_ROW], z.x, a0);
            a1 = fmaf(AsQ[(i4 * 4 + 1) * AS_ROW], z.y, a1);
            a0 = fmaf(AsQ[(i4 * 4 + 2) * AS_ROW], z.z, a0);
            a1 = fmaf(AsQ[(i4 * 4 + 3) * AS_ROW], z.w, a1);
        }
#pragma unroll
        for (int i4 = 0; i4 < 8; i4++) {
            float4 z = *(const float4*)(Zq + 32 + i4 * 4);
            a0 = fmaf(regA[i4 * 4 + 0], z.x, a0);
            a1 = fmaf(regA[i4 * 4 + 1], z.y, a1);
            a0 = fmaf(regA[i4 * 4 + 2], z.z, a0);
            a1 = fmaf(regA[i4 * 4 + 3], z.w, a1);
        }
        pred[tid] = a0 + a1;
        __syncthreads();
        if (q == 0) {
            float v = pred[k] + pred[256 + k] + pred[512 + k] + pred[768 + k];
            Zs[k] = 0.9f * v + 0.1f * Ss[k];
        }
        __syncthreads();
    }
    if (q == 0) g_Z[b][k] = Zs[k];
}

// ---------------------------------------------------------------------------
// K3: z_gene + MLP + out. 157 blocks x 1024 threads, 32 genes/block.
// Workers: (jh = tid>>8) x (p = tid&7) x (gl = (tid&255)>>3): 64-j partial
// dots into zpart; 256-thread tail does 4-way sum + MLP + store.
// ---------------------------------------------------------------------------
__global__ __launch_bounds__(1024) void k3_out(
    const float* __restrict__ ctl,
    const float* __restrict__ t,
    const float* __restrict__ M,
    const float* __restrict__ W1,
    const float* __restrict__ b1,
    const float* __restrict__ W2,
    float* __restrict__ out)
{
    extern __shared__ float s3[];
    float*  Ms    = s3;                          // 32*257 = 8224
    float2* Zp    = (float2*)(s3 + 8224);        // [K][8]
    float2* zpart = (float2*)(s3 + 8224 + 4096); // [4][256]
    float*  W1s   = s3 + 8224 + 4096 + 2048;     // 192
    float*  b1s   = W1s + 192;
    float*  W2s   = b1s + HID;
    float*  coffs = W2s + HID;                   // 16

    const int tid = threadIdx.x;
    const int g0  = blockIdx.x * GT;

    for (int i = tid; i < GT * 64; i += 1024) {
        int gl = i >> 6, jq = i & 63;
        int g = g0 + gl;
        float4 v = (g < G) ? *(const float4*)(M + (size_t)g * K + 4 * jq)
                           : make_float4(0.f, 0.f, 0.f, 0.f);
        float* d = Ms + gl * 257 + 4 * jq;
        d[0] = v.x; d[1] = v.y; d[2] = v.z; d[3] = v.w;
    }
    for (int i = tid; i < K * 8; i += 1024) {
        int j = i >> 3, p = i & 7;
        Zp[i] = make_float2(g_Z[p][j], g_Z[p + 8][j]);
    }
    if (tid < 3 * HID) W1s[tid] = W1[tid];
    if (tid < HID) { b1s[tid] = b1[tid]; W2s[tid] = W2[tid]; }
    if (tid < B)   coffs[tid] = g_coff[tid];
    __syncthreads();

    {
        const int jh = tid >> 8;
        const int r  = tid & 255;
        const int p  = r & 7;
        const int gl = r >> 3;
        const int j0 = jh * 64;
        float z0 = 0.f, z1 = 0.f;
        const float*  Mrow = Ms + gl * 257;
        const float2* Zw   = Zp + p;
#pragma unroll 8
        for (int j = j0; j < j0 + 64; j++) {
            float  m  = Mrow[j];
            float2 zz = Zw[j * 8];
            z0 = fmaf(zz.x, m, z0);
            z1 = fmaf(zz.y, m, z1);
        }
        zpart[jh * 256 + r] = make_float2(z0, z1);
    }
    __syncthreads();

    if (tid < 256) {
        int p = tid & 7, gl = tid >> 3;
        int g = g0 + gl;
        if (g < G) {
            float2 pa = zpart[tid],       pb = zpart[256 + tid];
            float2 pc = zpart[512 + tid], pd = zpart[768 + tid];
            float z0 = pa.x + pb.x + pc.x + pd.x;
            float z1 = pa.y + pb.y + pc.y + pd.y;
            float c0 = ctl[p * G + g], c1v = ctl[(p + 8) * G + g];
            float t0 = t[p * G + g],   t1v = t[(p + 8) * G + g];
            float y0 = coffs[p], y1 = coffs[p + 8];
#pragma unroll 8
            for (int j = 0; j < HID; j++) {
                float w1c = W1s[j], w1t = W1s[HID + j], w1z = W1s[2 * HID + j];
                float bbv = b1s[j], w2 = W2s[j];
                float v0 = fmaf(c0, w1c, fmaf(t0, w1t, fmaf(z0, w1z, bbv)));
                float v1 = fmaf(c1v, w1c, fmaf(t1v, w1t, fmaf(z1, w1z, bbv)));
                y0 = fmaf(fmaxf(v0, 0.f), w2, y0);
                y1 = fmaf(fmaxf(v1, 0.f), w2, y1);
            }
            out[p * G + g]       = y0;
            out[(p + 8) * G + g] = y1;
        }
    }
}
#define K3_SMEM ((8224 + 4096 + 2048 + 192 + HID + HID + B) * (int)sizeof(float))

// ---------------------------------------------------------------------------
// metadata order: ctl, drug_targets, cell_idx, drug_fp, M, A, W1, b1,
//                 cell_emb, W2, b2   -> output [B, G] float32
// ---------------------------------------------------------------------------
extern "C" void kernel_launch(void* const* d_in, const int* in_sizes, int n_in,
                              void* d_out, int out_size)
{
    const float* ctl      = (const float*)d_in[0];
    const float* tgt      = (const float*)d_in[1];
    const int*   cell_idx = (const int*)  d_in[2];
    // d_in[3] = drug_fp (unused by the model)
    const float* M        = (const float*)d_in[4];
    const float* A        = (const float*)d_in[5];
    const float* W1       = (const float*)d_in[6];
    const float* b1       = (const float*)d_in[7];
    const float* cell_emb = (const float*)d_in[8];
    const float* W2       = (const float*)d_in[9];
    const float* b2       = (const float*)d_in[10];
    float* out = (float*)d_out;

    const int k2_smem = K2_SMEM_FLOATS * (int)sizeof(float);
    cudaFuncSetAttribute(k1_maxpool,
                         cudaFuncAttributeMaxDynamicSharedMemorySize, K1_SMEM);
    cudaFuncSetAttribute(k2_appnp,
                         cudaFuncAttributeMaxDynamicSharedMemorySize, k2_smem);
    cudaFuncSetAttribute(k3_out,
                         cudaFuncAttributeMaxDynamicSharedMemorySize, K3_SMEM);

    k1_maxpool<<<NCHUNK, 1024, K1_SMEM>>>(tgt, M);
    k2_appnp<<<B, 1024, k2_smem>>>(A, cell_idx, cell_emb, W2, b2);
    k3_out<<<(G + GT - 1) / GT, 1024, K3_SMEM>>>(ctl, tgt, M, W1, b1, W2, out);
}